// round 15
// baseline (speedup 1.0000x reference)
#include <cuda_runtime.h>
#include <cuda_fp16.h>
#include <cstdint>
#include <math.h>

#define B_ 8
#define C_ 2048
#define F_ 512
#define THRESH 0.005f

// ---- scratch (device globals: no allocation allowed) ----
__device__ __half g_A[(size_t)B_ * C_ * C_];       // binary adjacency (fp16 0/1)
__device__ float  g_invn[B_ * C_];
__device__ float  g_deg[B_ * C_];
__device__ float  g_dinv[B_ * C_];
__device__ __half g_xhi[(size_t)B_ * C_ * F_];
__device__ __half g_xlo[(size_t)B_ * C_ * F_];
__device__ __half g_gT[(size_t)B_ * F_ * C_];      // (dinv*(h@W))^T  fp16
__device__ __half g_h2[(size_t)B_ * C_ * F_];      // hidden activations fp16
__device__ __half g_WT1[F_ * F_];                  // W1^T fp16
__device__ __half g_WT2[F_ * F_];                  // W2^T fp16

// =============================== helpers ===============================
__device__ __forceinline__ uint32_t smem_u32(const void* p) {
    uint32_t a;
    asm("{ .reg .u64 t; cvta.to.shared.u64 t, %1; cvt.u32.u64 %0, t; }" : "=r"(a) : "l"(p));
    return a;
}
#define CP_COMMIT() asm volatile("cp.async.commit_group;" ::: "memory")
#define CP_WAIT1()  asm volatile("cp.async.wait_group 1;" ::: "memory")
#define CP_WAIT0()  asm volatile("cp.async.wait_group 0;" ::: "memory")

__device__ __forceinline__ void mma_f16(float c[4], const uint32_t a[4], const uint32_t b[2]) {
    asm volatile(
        "mma.sync.aligned.m16n8k16.row.col.f32.f16.f16.f32 "
        "{%0,%1,%2,%3}, {%4,%5,%6,%7}, {%8,%9}, {%0,%1,%2,%3};"
        : "+f"(c[0]), "+f"(c[1]), "+f"(c[2]), "+f"(c[3])
        : "r"(a[0]), "r"(a[1]), "r"(a[2]), "r"(a[3]), "r"(b[0]), "r"(b[1]));
}
__device__ __forceinline__ void ldsm4(uint32_t r[4], uint32_t addr) {
    asm volatile("ldmatrix.sync.aligned.m8n8.x4.shared.b16 {%0,%1,%2,%3}, [%4];"
        : "=r"(r[0]), "=r"(r[1]), "=r"(r[2]), "=r"(r[3]) : "r"(addr));
}
// swizzled byte offset inside one 128-row tile; KCC = K-chunk width (32 or 64 halves)
template <int KCC>
__device__ __forceinline__ uint32_t swz(int row, int seg) {
    if (KCC == 64) return (uint32_t)(row * 128 + ((seg ^ (row & 7)) << 4));
    return (uint32_t)(row * 64 + ((seg ^ ((row >> 1) & 3)) << 4));
}

// ====================== fp16 mma GEMM (128x128 tile, persistent multi-tile) ======================
// All operands row-major with K contiguous: Aop[m][k] (lda), Bop[n][k] (ldb).
// MODE 0: GRAM (symmetric blocks, KC32, WPT=4 over batch): 3 passes; binarize; mirror; deg
// MODE 2: HWT  (KC64, WPT=2 over rows) g = h@WT ; epi: *dinv, transpose -> gT fp16
// MODE 1: AH   (KC64, WPT=2 over batch) A@gT    ; epi: relu(*dinv[m]+bias) -> fp16
// MODE 3: AH   same, epi -> fp32

template <int MODE>
__global__ __launch_bounds__(256, 2) void mma_gemm(
    const __half* __restrict__ a0, const __half* __restrict__ a1,
    const __half* __restrict__ b0, const __half* __restrict__ b1,
    int lda, int ldb, int K,
    size_t aBatch, size_t bBatch,
    const float* __restrict__ aux, int auxBatch,
    const float* __restrict__ bias,
    void* __restrict__ out0,
    int ldo, size_t oBatch,
    float* __restrict__ deg)
{
    constexpr int NA   = (MODE == 0) ? 2 : 1;
    constexpr int NB   = (MODE == 0) ? 2 : 1;
    constexpr int NOPS = NA + NB;
    constexpr int KCC  = (MODE == 0) ? 32 : 64;
    constexpr int TB   = 128 * KCC * 2;          // tile bytes
    constexpr int NKS  = KCC / 16;
    constexpr int WPT  = (MODE == 0) ? 4 : 2;    // tiles per CTA

    int tid = threadIdx.x, wid = tid >> 5, lane = tid & 31;
    int wm = wid & 1, wn = wid >> 1;          // warp tile 64x32
    int g = lane >> 2, t = lane & 3;

    int a_row = ((lane >> 3) & 1) * 8 + (lane & 7);
    int a_sg  = lane >> 4;
    int b_row = ((lane >> 4) & 1) * 8 + (lane & 7);
    int b_sg  = (lane >> 3) & 1;

    extern __shared__ __half sm[];
    uint32_t smb = smem_u32(sm);

    const __half* ops[NOPS];
    int ldv[NOPS];

    float acc[4][4][4];
    uint32_t afr[NA][4][4];
    uint32_t bfr0[4][2], bfr1[4][2];
    uint32_t a2[2][4][4];
    uint32_t b2[2][4][2];

    for (int w = 0; w < WPT; w++) {
        if (w) __syncthreads();                 // smem WAR vs previous tile

        int m0, n0, b;
        if (MODE == 0) {
            int idx = blockIdx.x, bi = 0;
            while (idx >= (C_ / 128 - bi)) { idx -= (C_ / 128 - bi); bi++; }
            m0 = bi * 128; n0 = (bi + idx) * 128;
            b = blockIdx.z + w * 2;             // gridDim.z == 2
        } else if (MODE == 2) {
            m0 = ((int)blockIdx.y + w * 64) * 128;  // gridDim.y == 64
            n0 = blockIdx.x * 128; b = 0;
        } else {
            m0 = blockIdx.y * 128; n0 = blockIdx.x * 128;
            b = blockIdx.z + w * 4;             // gridDim.z == 4
        }
        const bool diag = (MODE == 0) && (m0 == n0);
        const int nload = diag ? NA : NOPS;

        ops[0] = a0 + (size_t)b * aBatch + (size_t)m0 * lda; ldv[0] = lda;
        if (NA == 2) { ops[1] = a1 + (size_t)b * aBatch + (size_t)m0 * lda; ldv[1] = lda; }
        ops[NA] = b0 + (size_t)b * bBatch + (size_t)n0 * ldb; ldv[NA] = ldb;
        if (NB == 2) { ops[NA + 1] = b1 + (size_t)b * bBatch + (size_t)n0 * ldb; ldv[NA + 1] = ldb; }

        auto load_tile = [&](int op, int buf, int k0) {
            uint32_t st = smb + (uint32_t)(buf * NOPS + op) * TB;
            const __half* src = ops[op] + k0;
            int ld = ldv[op];
            constexpr int ITER = (128 * KCC / 8) / 256;
#pragma unroll
            for (int i2 = 0; i2 < ITER; i2++) {
                int idx = tid + i2 * 256;
                int row, seg;
                if (KCC == 64) { row = idx >> 3; seg = idx & 7; }
                else           { row = idx >> 2; seg = idx & 3; }
                const __half* gp = src + (size_t)row * ld + seg * 8;
                uint32_t sa = st + swz<KCC>(row, seg);
                asm volatile("cp.async.cg.shared.global [%0], [%1], 16;" :: "r"(sa), "l"(gp) : "memory");
            }
        };

#pragma unroll
        for (int i = 0; i < 4; i++)
#pragma unroll
            for (int j = 0; j < 4; j++)
#pragma unroll
                for (int r = 0; r < 4; r++) acc[i][j][r] = 0.f;

        auto compute4 = [&](int buf) {
            uint32_t tb = smb + (uint32_t)(buf * NOPS) * TB;
            uint32_t tB0 = tb + (diag ? 0u : 2u * TB);     // alias B->A on diagonal
            uint32_t tB1 = tb + (diag ? 1u : 3u) * TB;
#pragma unroll
            for (int ks = 0; ks < NKS; ks++) {
                int segA = 2 * ks + a_sg;
                int segB = 2 * ks + b_sg;
#pragma unroll
                for (int i = 0; i < 4; i++)
                    ldsm4(afr[0][i], tb + swz<KCC>(wm * 64 + i * 16 + a_row, segA));
#pragma unroll
                for (int i = 0; i < 4; i++)
                    ldsm4(afr[NA - 1][i], tb + TB + swz<KCC>(wm * 64 + i * 16 + a_row, segA));
                ldsm4(&bfr0[0][0], tB0 + swz<KCC>(wn * 32 + b_row, segB));
                ldsm4(&bfr0[2][0], tB0 + swz<KCC>(wn * 32 + 16 + b_row, segB));
                ldsm4(&bfr1[0][0], tB1 + swz<KCC>(wn * 32 + b_row, segB));
                ldsm4(&bfr1[2][0], tB1 + swz<KCC>(wn * 32 + 16 + b_row, segB));
#pragma unroll
                for (int i = 0; i < 4; i++)
#pragma unroll
                    for (int j = 0; j < 4; j++) mma_f16(acc[i][j], afr[0][i], bfr0[j]);
#pragma unroll
                for (int i = 0; i < 4; i++)
#pragma unroll
                    for (int j = 0; j < 4; j++) mma_f16(acc[i][j], afr[NA - 1][i], bfr0[j]);
#pragma unroll
                for (int i = 0; i < 4; i++)
#pragma unroll
                    for (int j = 0; j < 4; j++) mma_f16(acc[i][j], afr[0][i], bfr1[j]);
            }
        };

        auto compute2 = [&](int buf) {
            uint32_t tb = smb + (uint32_t)(buf * NOPS) * TB;
            uint32_t tB0 = tb + TB;
            {
                int segA = a_sg, segB = b_sg;
#pragma unroll
                for (int i = 0; i < 4; i++)
                    ldsm4(a2[0][i], tb + swz<KCC>(wm * 64 + i * 16 + a_row, segA));
                ldsm4(&b2[0][0][0], tB0 + swz<KCC>(wn * 32 + b_row, segB));
                ldsm4(&b2[0][2][0], tB0 + swz<KCC>(wn * 32 + 16 + b_row, segB));
            }
#pragma unroll
            for (int ks = 0; ks < NKS; ks++) {
                int cur = ks & 1, nxt = cur ^ 1;
                if (ks + 1 < NKS) {
                    int segA = 2 * (ks + 1) + a_sg;
                    int segB = 2 * (ks + 1) + b_sg;
#pragma unroll
                    for (int i = 0; i < 4; i++)
                        ldsm4(a2[nxt][i], tb + swz<KCC>(wm * 64 + i * 16 + a_row, segA));
                    ldsm4(&b2[nxt][0][0], tB0 + swz<KCC>(wn * 32 + b_row, segB));
                    ldsm4(&b2[nxt][2][0], tB0 + swz<KCC>(wn * 32 + 16 + b_row, segB));
                }
#pragma unroll
                for (int i = 0; i < 4; i++)
#pragma unroll
                    for (int j = 0; j < 4; j++) mma_f16(acc[i][j], a2[cur][i], b2[cur][j]);
            }
        };

        const int NC = K / KCC;
        for (int op = 0; op < nload; op++) load_tile(op, 0, 0);
        CP_COMMIT();
        if (NC > 1) {
            for (int op = 0; op < nload; op++) load_tile(op, 1, KCC);
            CP_COMMIT();
        }
        for (int c = 0; c < NC; c++) {
            if (c + 1 < NC) { CP_WAIT1(); } else { CP_WAIT0(); }
            __syncthreads();
            if (c + 2 < NC) {
                for (int op = 0; op < nload; op++) load_tile(op, (c + 2) % 3, (c + 2) * KCC);
                CP_COMMIT();
            }
            if (NOPS == 2) compute2(c % 3);
            else           compute4(c % 3);
        }

        // ------------------------------- epilogues -------------------------------
        if (MODE == 0) {
            const float* inb = aux + (size_t)b * auxBatch;
            __half* Ab = (__half*)out0 + (size_t)b * oBatch;
            float* degb = deg + (size_t)b * C_;
            float v[4][4][4];
#pragma unroll
            for (int i = 0; i < 4; i++) {
                int r0 = m0 + wm * 64 + i * 16 + g;
                float rs0 = inb[r0], rs1 = inb[r0 + 8];
#pragma unroll
                for (int j = 0; j < 4; j++) {
                    int cl = n0 + wn * 32 + j * 8 + t * 2;
                    float j0 = inb[cl], j1 = inb[cl + 1];
                    v[i][j][0] = (acc[i][j][0] * rs0 * j0 > THRESH) ? 1.f : 0.f;
                    v[i][j][1] = (acc[i][j][1] * rs0 * j1 > THRESH) ? 1.f : 0.f;
                    v[i][j][2] = (acc[i][j][2] * rs1 * j0 > THRESH) ? 1.f : 0.f;
                    v[i][j][3] = (acc[i][j][3] * rs1 * j1 > THRESH) ? 1.f : 0.f;
                    *(__half2*)(Ab + (size_t)r0 * ldo + cl)       = __floats2half2_rn(v[i][j][0], v[i][j][1]);
                    *(__half2*)(Ab + (size_t)(r0 + 8) * ldo + cl) = __floats2half2_rn(v[i][j][2], v[i][j][3]);
                }
            }
#pragma unroll
            for (int i = 0; i < 4; i++) {
                float s0 = 0.f, s1 = 0.f;
#pragma unroll
                for (int j = 0; j < 4; j++) {
                    s0 += v[i][j][0] + v[i][j][1];
                    s1 += v[i][j][2] + v[i][j][3];
                }
                s0 += __shfl_xor_sync(0xFFFFFFFFu, s0, 1); s0 += __shfl_xor_sync(0xFFFFFFFFu, s0, 2);
                s1 += __shfl_xor_sync(0xFFFFFFFFu, s1, 1); s1 += __shfl_xor_sync(0xFFFFFFFFu, s1, 2);
                if (t == 0) {
                    atomicAdd(&degb[m0 + wm * 64 + i * 16 + g], s0);
                    atomicAdd(&degb[m0 + wm * 64 + i * 16 + g + 8], s1);
                }
            }
            if (m0 != n0) {
#pragma unroll
                for (int j = 0; j < 4; j++) {
                    float c0 = 0.f, c1 = 0.f;
#pragma unroll
                    for (int i = 0; i < 4; i++) {
                        c0 += v[i][j][0] + v[i][j][2];
                        c1 += v[i][j][1] + v[i][j][3];
                    }
                    c0 += __shfl_xor_sync(0xFFFFFFFFu, c0, 4); c0 += __shfl_xor_sync(0xFFFFFFFFu, c0, 8); c0 += __shfl_xor_sync(0xFFFFFFFFu, c0, 16);
                    c1 += __shfl_xor_sync(0xFFFFFFFFu, c1, 4); c1 += __shfl_xor_sync(0xFFFFFFFFu, c1, 8); c1 += __shfl_xor_sync(0xFFFFFFFFu, c1, 16);
                    if (lane < 4) {
                        atomicAdd(&degb[n0 + wn * 32 + j * 8 + t * 2], c0);
                        atomicAdd(&degb[n0 + wn * 32 + j * 8 + t * 2 + 1], c1);
                    }
                }
                __syncthreads();
                float* stage = (float*)sm;                 // 128 x 129 floats
#pragma unroll
                for (int i = 0; i < 4; i++) {
                    int rr = wm * 64 + i * 16 + g;
#pragma unroll
                    for (int j = 0; j < 4; j++) {
                        int cc = wn * 32 + j * 8 + t * 2;
                        stage[rr * 129 + cc]           = v[i][j][0];
                        stage[rr * 129 + cc + 1]       = v[i][j][1];
                        stage[(rr + 8) * 129 + cc]     = v[i][j][2];
                        stage[(rr + 8) * 129 + cc + 1] = v[i][j][3];
                    }
                }
                __syncthreads();
#pragma unroll
                for (int q = 0; q < 16; q++) {
                    int idx = tid + q * 256;
                    int r = idx >> 5;
                    int c4 = (idx & 31) * 4;
                    float f0 = stage[(c4 + 0) * 129 + r];
                    float f1 = stage[(c4 + 1) * 129 + r];
                    float f2 = stage[(c4 + 2) * 129 + r];
                    float f3 = stage[(c4 + 3) * 129 + r];
                    __half* dst = Ab + (size_t)(n0 + r) * ldo + m0 + c4;
                    ((__half2*)dst)[0] = __floats2half2_rn(f0, f1);
                    ((__half2*)dst)[1] = __floats2half2_rn(f2, f3);
                }
            }
        } else if (MODE == 2) {
            // g = h@WT row-scale by dinv[global row], transpose -> gT fp16 [b][f][c]
            const float* db = aux;                       // flattened dinv, index m0+row
            __syncthreads();
            float* stage = (float*)sm;                   // 128 x 129 floats
#pragma unroll
            for (int i = 0; i < 4; i++) {
                int rr = wm * 64 + i * 16 + g;
                float d0 = db[m0 + rr], d1 = db[m0 + rr + 8];
#pragma unroll
                for (int j = 0; j < 4; j++) {
                    int cc = wn * 32 + j * 8 + t * 2;
                    stage[rr * 129 + cc]           = acc[i][j][0] * d0;
                    stage[rr * 129 + cc + 1]       = acc[i][j][1] * d0;
                    stage[(rr + 8) * 129 + cc]     = acc[i][j][2] * d1;
                    stage[(rr + 8) * 129 + cc + 1] = acc[i][j][3] * d1;
                }
            }
            __syncthreads();
            int bb = m0 / C_;
            int cb = m0 % C_;
            __half* ghi = (__half*)out0;
#pragma unroll
            for (int q = 0; q < 16; q++) {
                int idx = tid + q * 256;
                int r = idx >> 5;                         // local f
                int c4 = (idx & 31) * 4;                  // local c, 4-aligned
                float f0 = stage[(c4 + 0) * 129 + r];
                float f1 = stage[(c4 + 1) * 129 + r];
                float f2 = stage[(c4 + 2) * 129 + r];
                float f3 = stage[(c4 + 3) * 129 + r];
                size_t o = ((size_t)bb * F_ + n0 + r) * C_ + cb + c4;
                ((__half2*)(ghi + o))[0] = __floats2half2_rn(f0, f1);
                ((__half2*)(ghi + o))[1] = __floats2half2_rn(f2, f3);
            }
        } else {
            // AH: v = relu(acc * dinv[m] + bias)
            const float* db = aux + (size_t)b * auxBatch;
            float bs = bias[0];
#pragma unroll
            for (int i = 0; i < 4; i++) {
                int r0 = m0 + wm * 64 + i * 16 + g;
                float rs0 = db[r0], rs1 = db[r0 + 8];
#pragma unroll
                for (int j = 0; j < 4; j++) {
                    int cl = n0 + wn * 32 + j * 8 + t * 2;
                    float v00 = fmaxf(acc[i][j][0] * rs0 + bs, 0.f);
                    float v01 = fmaxf(acc[i][j][1] * rs0 + bs, 0.f);
                    float v10 = fmaxf(acc[i][j][2] * rs1 + bs, 0.f);
                    float v11 = fmaxf(acc[i][j][3] * rs1 + bs, 0.f);
                    if (MODE == 1) {
                        __half* o0 = (__half*)out0 + (size_t)b * oBatch;
                        *(__half2*)(o0 + (size_t)r0 * ldo + cl)       = __floats2half2_rn(v00, v01);
                        *(__half2*)(o0 + (size_t)(r0 + 8) * ldo + cl) = __floats2half2_rn(v10, v11);
                    } else {
                        float* o = (float*)out0 + (size_t)b * oBatch;
                        *(float2*)(o + (size_t)r0 * ldo + cl)       = make_float2(v00, v01);
                        *(float2*)(o + (size_t)(r0 + 8) * ldo + cl) = make_float2(v10, v11);
                    }
                }
            }
        }
    }
}

// =============================== small kernels ==============================
// fused: row inv-norms + fp16 hi/lo split of x + deg zeroing
__global__ void norm_split(const float* __restrict__ x, float* __restrict__ invn,
                           __half* __restrict__ hi, __half* __restrict__ lo,
                           float* __restrict__ deg) {
    int row = blockIdx.x;
    const float* xr = x + (size_t)row * F_;
    float4 v = ((const float4*)xr)[threadIdx.x];
    float s = v.x * v.x + v.y * v.y + v.z * v.z + v.w * v.w;
#pragma unroll
    for (int o = 16; o > 0; o >>= 1) s += __shfl_xor_sync(0xFFFFFFFFu, s, o);
    __shared__ float red[4];
    if ((threadIdx.x & 31) == 0) red[threadIdx.x >> 5] = s;
    __syncthreads();
    if (threadIdx.x == 0) {
        invn[row] = 1.0f / sqrtf(red[0] + red[1] + red[2] + red[3]);
        deg[row] = 0.f;
    }

    __half h0 = __float2half_rn(v.x), h1 = __float2half_rn(v.y);
    __half h2 = __float2half_rn(v.z), h3 = __float2half_rn(v.w);
    size_t o = (size_t)row * F_ + threadIdx.x * 4;
    *(__half2*)(hi + o)     = __halves2half2(h0, h1);
    *(__half2*)(hi + o + 2) = __halves2half2(h2, h3);
    *(__half2*)(lo + o)     = __floats2half2_rn(v.x - __half2float(h0), v.y - __half2float(h1));
    *(__half2*)(lo + o + 2) = __floats2half2_rn(v.z - __half2float(h2), v.w - __half2float(h3));
}

__global__ void dinv_kernel(const float* __restrict__ deg, float* __restrict__ dinv) {
    int i = blockIdx.x * 256 + threadIdx.x;
    dinv[i] = 1.0f / sqrtf(deg[i]);
}

// W[f,g] -> WT[g,f] single fp16
__global__ void wtrans_kernel(const float* __restrict__ W, __half* __restrict__ hi) {
    __shared__ float tsm[32][33];
    int g0 = blockIdx.x * 32, f0 = blockIdx.y * 32;
#pragma unroll
    for (int k = 0; k < 4; k++) {
        int f = f0 + threadIdx.y + k * 8;
        tsm[threadIdx.x][threadIdx.y + k * 8] = W[(size_t)f * F_ + g0 + threadIdx.x];
    }
    __syncthreads();
#pragma unroll
    for (int k = 0; k < 4; k++) {
        int gg = g0 + threadIdx.y + k * 8;
        hi[(size_t)gg * F_ + f0 + threadIdx.x] = __float2half_rn(tsm[threadIdx.y + k * 8][threadIdx.x]);
    }
}

// ============================================================================
extern "C" void kernel_launch(void* const* d_in, const int* in_sizes, int n_in,
                              void* d_out, int out_size) {
    const float* x  = (const float*)d_in[0];
    const float* W1 = (const float*)d_in[1];
    const float* b1 = (const float*)d_in[2];
    const float* W2 = (const float*)d_in[3];
    const float* b2 = (const float*)d_in[4];
    float* out = (float*)d_out;

    __half *pA, *pxhi, *pxlo, *pgT, *ph2, *pWT1, *pWT2;
    float *pinvn, *pdeg, *pdinv;
    cudaGetSymbolAddress((void**)&pA,    g_A);
    cudaGetSymbolAddress((void**)&pinvn, g_invn);
    cudaGetSymbolAddress((void**)&pdeg,  g_deg);
    cudaGetSymbolAddress((void**)&pdinv, g_dinv);
    cudaGetSymbolAddress((void**)&pxhi,  g_xhi);
    cudaGetSymbolAddress((void**)&pxlo,  g_xlo);
    cudaGetSymbolAddress((void**)&pgT,   g_gT);
    cudaGetSymbolAddress((void**)&ph2,   g_h2);
    cudaGetSymbolAddress((void**)&pWT1,  g_WT1);
    cudaGetSymbolAddress((void**)&pWT2,  g_WT2);

    const int smem0 = 4 * 3 * (128 * 32 * 2);   // 98304 B (GRAM: 4 ops, KC32)
    const int smem1 = 2 * 3 * (128 * 64 * 2);   // 98304 B (HWT/AH: 2 ops, KC64)
    cudaFuncSetAttribute(mma_gemm<0>, cudaFuncAttributeMaxDynamicSharedMemorySize, smem0);
    cudaFuncSetAttribute(mma_gemm<1>, cudaFuncAttributeMaxDynamicSharedMemorySize, smem1);
    cudaFuncSetAttribute(mma_gemm<2>, cudaFuncAttributeMaxDynamicSharedMemorySize, smem1);
    cudaFuncSetAttribute(mma_gemm<3>, cudaFuncAttributeMaxDynamicSharedMemorySize, smem1);

    const int NBLK = C_ / 128;                       // 16
    const int NTRI = NBLK * (NBLK + 1) / 2;          // 136

    // ---- input-only preprocessing (no cross dependencies) ----
    wtrans_kernel<<<dim3(F_ / 32, F_ / 32), dim3(32, 8)>>>(W1, pWT1);
    wtrans_kernel<<<dim3(F_ / 32, F_ / 32), dim3(32, 8)>>>(W2, pWT2);
    norm_split<<<B_ * C_, 128>>>(x, pinvn, pxhi, pxlo, pdeg);

    // ---- Laplacian ----  (272 CTAs x 4 tiles: one wave)
    mma_gemm<0><<<dim3(NTRI, 1, 2), 256, smem0>>>(
        pxhi, pxlo, pxhi, pxlo, F_, F_, F_,
        (size_t)C_ * F_, (size_t)C_ * F_, pinvn, C_, nullptr,
        pA, C_, (size_t)C_ * C_, pdeg);
    dinv_kernel<<<(B_ * C_) / 256, 256>>>(pdeg, pdinv);

    // ---- layer 1: relu(L @ (x @ W1) + b1) ----  (256 CTAs x 2 tiles each)
    mma_gemm<2><<<dim3(F_ / 128, 64, 1), 256, smem1>>>(
        pxhi, nullptr, pWT1, nullptr, F_, F_, F_,
        0, 0, pdinv, 0, nullptr,
        pgT, C_, 0, nullptr);
    mma_gemm<1><<<dim3(F_ / 128, C_ / 128, 4), 256, smem1>>>(
        pA, nullptr, pgT, nullptr, C_, C_, C_,
        (size_t)C_ * C_, (size_t)F_ * C_, pdinv, C_, b1,
        ph2, F_, (size_t)C_ * F_, nullptr);

    // ---- layer 2: relu(L @ (h2 @ W2) + b2) ----
    mma_gemm<2><<<dim3(F_ / 128, 64, 1), 256, smem1>>>(
        ph2, nullptr, pWT2, nullptr, F_, F_, F_,
        0, 0, pdinv, 0, nullptr,
        pgT, C_, 0, nullptr);
    mma_gemm<3><<<dim3(F_ / 128, C_ / 128, 4), 256, smem1>>>(
        pA, nullptr, pgT, nullptr, C_, C_, C_,
        (size_t)C_ * C_, (size_t)F_ * C_, pdinv, C_, b2,
        out, F_, (size_t)C_ * F_, nullptr);
}

// round 16
// speedup vs baseline: 1.0568x; 1.0568x over previous
#include <cuda_runtime.h>
#include <cuda_fp16.h>
#include <cstdint>
#include <math.h>

#define B_ 8
#define C_ 2048
#define F_ 512
#define THRESH 0.005f

// ---- scratch (device globals: no allocation allowed) ----
__device__ __half g_A[(size_t)B_ * C_ * C_];       // binary adjacency (fp16 0/1)
__device__ float  g_invn[B_ * C_];
__device__ float  g_deg[B_ * C_];
__device__ float  g_dinv[B_ * C_];
__device__ __half g_xhi[(size_t)B_ * C_ * F_];
__device__ __half g_xlo[(size_t)B_ * C_ * F_];
__device__ __half g_gT[(size_t)B_ * F_ * C_];      // (dinv*(h@W))^T  fp16
__device__ __half g_h2[(size_t)B_ * C_ * F_];      // hidden activations fp16
__device__ __half g_WT1[F_ * F_];                  // W1^T fp16
__device__ __half g_WT2[F_ * F_];                  // W2^T fp16

// =============================== helpers ===============================
__device__ __forceinline__ uint32_t smem_u32(const void* p) {
    uint32_t a;
    asm("{ .reg .u64 t; cvta.to.shared.u64 t, %1; cvt.u32.u64 %0, t; }" : "=r"(a) : "l"(p));
    return a;
}
#define CP_COMMIT() asm volatile("cp.async.commit_group;" ::: "memory")
#define CP_WAIT1()  asm volatile("cp.async.wait_group 1;" ::: "memory")
#define CP_WAIT0()  asm volatile("cp.async.wait_group 0;" ::: "memory")

__device__ __forceinline__ void mma_f16(float c[4], const uint32_t a[4], const uint32_t b[2]) {
    asm volatile(
        "mma.sync.aligned.m16n8k16.row.col.f32.f16.f16.f32 "
        "{%0,%1,%2,%3}, {%4,%5,%6,%7}, {%8,%9}, {%0,%1,%2,%3};"
        : "+f"(c[0]), "+f"(c[1]), "+f"(c[2]), "+f"(c[3])
        : "r"(a[0]), "r"(a[1]), "r"(a[2]), "r"(a[3]), "r"(b[0]), "r"(b[1]));
}
__device__ __forceinline__ void ldsm4(uint32_t r[4], uint32_t addr) {
    asm volatile("ldmatrix.sync.aligned.m8n8.x4.shared.b16 {%0,%1,%2,%3}, [%4];"
        : "=r"(r[0]), "=r"(r[1]), "=r"(r[2]), "=r"(r[3]) : "r"(addr));
}
// swizzled byte offset inside one 128-row tile; KCC = K-chunk width (32 or 64 halves)
template <int KCC>
__device__ __forceinline__ uint32_t swz(int row, int seg) {
    if (KCC == 64) return (uint32_t)(row * 128 + ((seg ^ (row & 7)) << 4));
    return (uint32_t)(row * 64 + ((seg ^ ((row >> 1) & 3)) << 4));
}

// ====================== fp16 mma GEMM (128x128 tile) ======================
// All operands row-major with K contiguous: Aop[m][k] (lda), Bop[n][k] (ldb).
// MODE 0: GRAM (symmetric blocks, KC32): NA=2,NB=2, 3 passes; binarize; mirror; deg
//         diagonal blocks alias B tiles to A tiles (identical data, half the loads)
// MODE 2: HWT  (KC64) NA=1,NB=1: g = h@WT ; epi: *dinv[row], transpose -> gT fp16
// MODE 1: AH   (KC64) NA=1,NB=1: A@gT     ; epi: relu(*dinv[m]+bias) -> fp16
// MODE 3: AH   (KC64) same, epi -> fp32

template <int MODE>
__global__ __launch_bounds__(256, 2) void mma_gemm(
    const __half* __restrict__ a0, const __half* __restrict__ a1,
    const __half* __restrict__ b0, const __half* __restrict__ b1,
    int lda, int ldb, int K,
    size_t aBatch, size_t bBatch,
    const float* __restrict__ aux, int auxBatch,
    const float* __restrict__ bias,
    void* __restrict__ out0,
    int ldo, size_t oBatch,
    float* __restrict__ deg)
{
    constexpr int NA   = (MODE == 0) ? 2 : 1;
    constexpr int NB   = (MODE == 0) ? 2 : 1;
    constexpr int NOPS = NA + NB;
    constexpr int KCC  = (MODE == 0) ? 32 : 64;
    constexpr int TB   = 128 * KCC * 2;          // tile bytes
    constexpr int NKS  = KCC / 16;

    int m0, n0, b = blockIdx.z;
    if (MODE == 0) {
        int idx = blockIdx.x, bi = 0;
        while (idx >= (C_ / 128 - bi)) { idx -= (C_ / 128 - bi); bi++; }
        m0 = bi * 128; n0 = (bi + idx) * 128;
    } else {
        m0 = blockIdx.y * 128; n0 = blockIdx.x * 128;
    }
    const bool diag = (MODE == 0) && (m0 == n0);
    const int nload = diag ? NA : NOPS;          // diagonal: skip B tile loads

    int tid = threadIdx.x, wid = tid >> 5, lane = tid & 31;
    int wm = wid & 1, wn = wid >> 1;          // warp tile 64x32
    int g = lane >> 2, t = lane & 3;

    const __half* ops[NOPS];
    int ldv[NOPS];
    ops[0] = a0 + (size_t)b * aBatch + (size_t)m0 * lda; ldv[0] = lda;
    if (NA == 2) { ops[1] = a1 + (size_t)b * aBatch + (size_t)m0 * lda; ldv[1] = lda; }
    ops[NA] = b0 + (size_t)b * bBatch + (size_t)n0 * ldb; ldv[NA] = ldb;
    if (NB == 2) { ops[NA + 1] = b1 + (size_t)b * bBatch + (size_t)n0 * ldb; ldv[NA + 1] = ldb; }

    extern __shared__ __half sm[];
    uint32_t smb = smem_u32(sm);

    auto load_tile = [&](int op, int buf, int k0) {
        uint32_t st = smb + (uint32_t)(buf * NOPS + op) * TB;
        const __half* src = ops[op] + k0;
        int ld = ldv[op];
        constexpr int ITER = (128 * KCC / 8) / 256;
#pragma unroll
        for (int i2 = 0; i2 < ITER; i2++) {
            int idx = tid + i2 * 256;
            int row, seg;
            if (KCC == 64) { row = idx >> 3; seg = idx & 7; }
            else           { row = idx >> 2; seg = idx & 3; }
            const __half* gp = src + (size_t)row * ld + seg * 8;
            uint32_t sa = st + swz<KCC>(row, seg);
            asm volatile("cp.async.cg.shared.global [%0], [%1], 16;" :: "r"(sa), "l"(gp) : "memory");
        }
    };

    float acc[4][4][4];
#pragma unroll
    for (int i = 0; i < 4; i++)
#pragma unroll
        for (int j = 0; j < 4; j++)
#pragma unroll
            for (int r = 0; r < 4; r++) acc[i][j][r] = 0.f;

    int a_row = ((lane >> 3) & 1) * 8 + (lane & 7);
    int a_sg  = lane >> 4;
    int b_row = ((lane >> 4) & 1) * 8 + (lane & 7);
    int b_sg  = (lane >> 3) & 1;

    // --- GRAM path frags ---
    uint32_t afr[NA][4][4];
    uint32_t bfr0[4][2], bfr1[4][2];

    // compute for NOPS==4 (GRAM)
    auto compute4 = [&](int buf) {
        uint32_t tb = smb + (uint32_t)(buf * NOPS) * TB;
        uint32_t tB0 = tb + (diag ? 0u : 2u * TB);     // alias B->A on diagonal
        uint32_t tB1 = tb + (diag ? 1u : 3u) * TB;
#pragma unroll
        for (int ks = 0; ks < NKS; ks++) {
            int segA = 2 * ks + a_sg;
            int segB = 2 * ks + b_sg;
#pragma unroll
            for (int i = 0; i < 4; i++)
                ldsm4(afr[0][i], tb + swz<KCC>(wm * 64 + i * 16 + a_row, segA));
#pragma unroll
            for (int i = 0; i < 4; i++)
                ldsm4(afr[NA - 1][i], tb + TB + swz<KCC>(wm * 64 + i * 16 + a_row, segA));
            ldsm4(&bfr0[0][0], tB0 + swz<KCC>(wn * 32 + b_row, segB));
            ldsm4(&bfr0[2][0], tB0 + swz<KCC>(wn * 32 + 16 + b_row, segB));
            ldsm4(&bfr1[0][0], tB1 + swz<KCC>(wn * 32 + b_row, segB));
            ldsm4(&bfr1[2][0], tB1 + swz<KCC>(wn * 32 + 16 + b_row, segB));
#pragma unroll
            for (int i = 0; i < 4; i++)
#pragma unroll
                for (int j = 0; j < 4; j++) mma_f16(acc[i][j], afr[0][i], bfr0[j]);
#pragma unroll
            for (int i = 0; i < 4; i++)
#pragma unroll
                for (int j = 0; j < 4; j++) mma_f16(acc[i][j], afr[NA - 1][i], bfr0[j]);
#pragma unroll
            for (int i = 0; i < 4; i++)
#pragma unroll
                for (int j = 0; j < 4; j++) mma_f16(acc[i][j], afr[0][i], bfr1[j]);
        }
    };

    // compute for NOPS==2 (AH/HWT): intra-chunk frag double-buffering
    uint32_t a2[2][4][4];
    uint32_t b2[2][4][2];
    auto compute2 = [&](int buf) {
        uint32_t tb = smb + (uint32_t)(buf * NOPS) * TB;
        uint32_t tB0 = tb + TB;
        {
            int segA = a_sg, segB = b_sg;
#pragma unroll
            for (int i = 0; i < 4; i++)
                ldsm4(a2[0][i], tb + swz<KCC>(wm * 64 + i * 16 + a_row, segA));
            ldsm4(&b2[0][0][0], tB0 + swz<KCC>(wn * 32 + b_row, segB));
            ldsm4(&b2[0][2][0], tB0 + swz<KCC>(wn * 32 + 16 + b_row, segB));
        }
#pragma unroll
        for (int ks = 0; ks < NKS; ks++) {
            int cur = ks & 1, nxt = cur ^ 1;
            if (ks + 1 < NKS) {
                int segA = 2 * (ks + 1) + a_sg;
                int segB = 2 * (ks + 1) + b_sg;
#pragma unroll
                for (int i = 0; i < 4; i++)
                    ldsm4(a2[nxt][i], tb + swz<KCC>(wm * 64 + i * 16 + a_row, segA));
                ldsm4(&b2[nxt][0][0], tB0 + swz<KCC>(wn * 32 + b_row, segB));
                ldsm4(&b2[nxt][2][0], tB0 + swz<KCC>(wn * 32 + 16 + b_row, segB));
            }
#pragma unroll
            for (int i = 0; i < 4; i++)
#pragma unroll
                for (int j = 0; j < 4; j++) mma_f16(acc[i][j], a2[cur][i], b2[cur][j]);
        }
    };

    const int NC = K / KCC;
    for (int op = 0; op < nload; op++) load_tile(op, 0, 0);
    CP_COMMIT();
    if (NC > 1) {
        for (int op = 0; op < nload; op++) load_tile(op, 1, KCC);
        CP_COMMIT();
    }
    for (int c = 0; c < NC; c++) {
        if (c + 1 < NC) { CP_WAIT1(); } else { CP_WAIT0(); }
        __syncthreads();
        if (c + 2 < NC) {
            for (int op = 0; op < nload; op++) load_tile(op, (c + 2) % 3, (c + 2) * KCC);
            CP_COMMIT();
        }
        if (NOPS == 2) compute2(c % 3);
        else           compute4(c % 3);
    }

    // ------------------------------- epilogues -------------------------------
    if (MODE == 0) {
        const float* inb = aux + (size_t)b * auxBatch;
        __half* Ab = (__half*)out0 + (size_t)b * oBatch;
        float* degb = deg + (size_t)b * C_;
        float v[4][4][4];
#pragma unroll
        for (int i = 0; i < 4; i++) {
            int r0 = m0 + wm * 64 + i * 16 + g;
            float rs0 = inb[r0], rs1 = inb[r0 + 8];
#pragma unroll
            for (int j = 0; j < 4; j++) {
                int cl = n0 + wn * 32 + j * 8 + t * 2;
                float j0 = inb[cl], j1 = inb[cl + 1];
                v[i][j][0] = (acc[i][j][0] * rs0 * j0 > THRESH) ? 1.f : 0.f;
                v[i][j][1] = (acc[i][j][1] * rs0 * j1 > THRESH) ? 1.f : 0.f;
                v[i][j][2] = (acc[i][j][2] * rs1 * j0 > THRESH) ? 1.f : 0.f;
                v[i][j][3] = (acc[i][j][3] * rs1 * j1 > THRESH) ? 1.f : 0.f;
                *(__half2*)(Ab + (size_t)r0 * ldo + cl)       = __floats2half2_rn(v[i][j][0], v[i][j][1]);
                *(__half2*)(Ab + (size_t)(r0 + 8) * ldo + cl) = __floats2half2_rn(v[i][j][2], v[i][j][3]);
            }
        }
#pragma unroll
        for (int i = 0; i < 4; i++) {
            float s0 = 0.f, s1 = 0.f;
#pragma unroll
            for (int j = 0; j < 4; j++) {
                s0 += v[i][j][0] + v[i][j][1];
                s1 += v[i][j][2] + v[i][j][3];
            }
            s0 += __shfl_xor_sync(0xFFFFFFFFu, s0, 1); s0 += __shfl_xor_sync(0xFFFFFFFFu, s0, 2);
            s1 += __shfl_xor_sync(0xFFFFFFFFu, s1, 1); s1 += __shfl_xor_sync(0xFFFFFFFFu, s1, 2);
            if (t == 0) {
                atomicAdd(&degb[m0 + wm * 64 + i * 16 + g], s0);
                atomicAdd(&degb[m0 + wm * 64 + i * 16 + g + 8], s1);
            }
        }
        if (m0 != n0) {
#pragma unroll
            for (int j = 0; j < 4; j++) {
                float c0 = 0.f, c1 = 0.f;
#pragma unroll
                for (int i = 0; i < 4; i++) {
                    c0 += v[i][j][0] + v[i][j][2];
                    c1 += v[i][j][1] + v[i][j][3];
                }
                c0 += __shfl_xor_sync(0xFFFFFFFFu, c0, 4); c0 += __shfl_xor_sync(0xFFFFFFFFu, c0, 8); c0 += __shfl_xor_sync(0xFFFFFFFFu, c0, 16);
                c1 += __shfl_xor_sync(0xFFFFFFFFu, c1, 4); c1 += __shfl_xor_sync(0xFFFFFFFFu, c1, 8); c1 += __shfl_xor_sync(0xFFFFFFFFu, c1, 16);
                if (lane < 4) {
                    atomicAdd(&degb[n0 + wn * 32 + j * 8 + t * 2], c0);
                    atomicAdd(&degb[n0 + wn * 32 + j * 8 + t * 2 + 1], c1);
                }
            }
            __syncthreads();
            float* stage = (float*)sm;                 // 128 x 129 floats
#pragma unroll
            for (int i = 0; i < 4; i++) {
                int rr = wm * 64 + i * 16 + g;
#pragma unroll
                for (int j = 0; j < 4; j++) {
                    int cc = wn * 32 + j * 8 + t * 2;
                    stage[rr * 129 + cc]           = v[i][j][0];
                    stage[rr * 129 + cc + 1]       = v[i][j][1];
                    stage[(rr + 8) * 129 + cc]     = v[i][j][2];
                    stage[(rr + 8) * 129 + cc + 1] = v[i][j][3];
                }
            }
            __syncthreads();
#pragma unroll
            for (int q = 0; q < 16; q++) {
                int idx = tid + q * 256;
                int r = idx >> 5;
                int c4 = (idx & 31) * 4;
                float f0 = stage[(c4 + 0) * 129 + r];
                float f1 = stage[(c4 + 1) * 129 + r];
                float f2 = stage[(c4 + 2) * 129 + r];
                float f3 = stage[(c4 + 3) * 129 + r];
                __half* dst = Ab + (size_t)(n0 + r) * ldo + m0 + c4;
                ((__half2*)dst)[0] = __floats2half2_rn(f0, f1);
                ((__half2*)dst)[1] = __floats2half2_rn(f2, f3);
            }
        }
    } else if (MODE == 2) {
        // g = h@WT row-scale by dinv[global row], transpose -> gT fp16 [b][f][c]
        const float* db = aux;                       // flattened dinv, index m0+row
        __syncthreads();
        float* stage = (float*)sm;                   // 128 x 129 floats
#pragma unroll
        for (int i = 0; i < 4; i++) {
            int rr = wm * 64 + i * 16 + g;
            float d0 = db[m0 + rr], d1 = db[m0 + rr + 8];
#pragma unroll
            for (int j = 0; j < 4; j++) {
                int cc = wn * 32 + j * 8 + t * 2;
                stage[rr * 129 + cc]           = acc[i][j][0] * d0;
                stage[rr * 129 + cc + 1]       = acc[i][j][1] * d0;
                stage[(rr + 8) * 129 + cc]     = acc[i][j][2] * d1;
                stage[(rr + 8) * 129 + cc + 1] = acc[i][j][3] * d1;
            }
        }
        __syncthreads();
        int bb = m0 / C_;
        int cb = m0 % C_;
        __half* ghi = (__half*)out0;
#pragma unroll
        for (int q = 0; q < 16; q++) {
            int idx = tid + q * 256;
            int r = idx >> 5;                         // local f
            int c4 = (idx & 31) * 4;                  // local c, 4-aligned
            float f0 = stage[(c4 + 0) * 129 + r];
            float f1 = stage[(c4 + 1) * 129 + r];
            float f2 = stage[(c4 + 2) * 129 + r];
            float f3 = stage[(c4 + 3) * 129 + r];
            size_t o = ((size_t)bb * F_ + n0 + r) * C_ + cb + c4;
            ((__half2*)(ghi + o))[0] = __floats2half2_rn(f0, f1);
            ((__half2*)(ghi + o))[1] = __floats2half2_rn(f2, f3);
        }
    } else {
        // AH: v = relu(acc * dinv[m] + bias)
        const float* db = aux + (size_t)b * auxBatch;
        float bs = bias[0];
#pragma unroll
        for (int i = 0; i < 4; i++) {
            int r0 = m0 + wm * 64 + i * 16 + g;
            float rs0 = db[r0], rs1 = db[r0 + 8];
#pragma unroll
            for (int j = 0; j < 4; j++) {
                int cl = n0 + wn * 32 + j * 8 + t * 2;
                float v00 = fmaxf(acc[i][j][0] * rs0 + bs, 0.f);
                float v01 = fmaxf(acc[i][j][1] * rs0 + bs, 0.f);
                float v10 = fmaxf(acc[i][j][2] * rs1 + bs, 0.f);
                float v11 = fmaxf(acc[i][j][3] * rs1 + bs, 0.f);
                if (MODE == 1) {
                    __half* o0 = (__half*)out0 + (size_t)b * oBatch;
                    *(__half2*)(o0 + (size_t)r0 * ldo + cl)       = __floats2half2_rn(v00, v01);
                    *(__half2*)(o0 + (size_t)(r0 + 8) * ldo + cl) = __floats2half2_rn(v10, v11);
                } else {
                    float* o = (float*)out0 + (size_t)b * oBatch;
                    *(float2*)(o + (size_t)r0 * ldo + cl)       = make_float2(v00, v01);
                    *(float2*)(o + (size_t)(r0 + 8) * ldo + cl) = make_float2(v10, v11);
                }
            }
        }
    }
}

// =============================== small kernels ==============================
// fused: row inv-norms + fp16 hi/lo split of x + deg zeroing
__global__ void norm_split(const float* __restrict__ x, float* __restrict__ invn,
                           __half* __restrict__ hi, __half* __restrict__ lo,
                           float* __restrict__ deg) {
    int row = blockIdx.x;
    const float* xr = x + (size_t)row * F_;
    float4 v = ((const float4*)xr)[threadIdx.x];
    float s = v.x * v.x + v.y * v.y + v.z * v.z + v.w * v.w;
#pragma unroll
    for (int o = 16; o > 0; o >>= 1) s += __shfl_xor_sync(0xFFFFFFFFu, s, o);
    __shared__ float red[4];
    if ((threadIdx.x & 31) == 0) red[threadIdx.x >> 5] = s;
    __syncthreads();
    if (threadIdx.x == 0) {
        invn[row] = 1.0f / sqrtf(red[0] + red[1] + red[2] + red[3]);
        deg[row] = 0.f;
    }

    __half h0 = __float2half_rn(v.x), h1 = __float2half_rn(v.y);
    __half h2 = __float2half_rn(v.z), h3 = __float2half_rn(v.w);
    size_t o = (size_t)row * F_ + threadIdx.x * 4;
    *(__half2*)(hi + o)     = __halves2half2(h0, h1);
    *(__half2*)(hi + o + 2) = __halves2half2(h2, h3);
    *(__half2*)(lo + o)     = __floats2half2_rn(v.x - __half2float(h0), v.y - __half2float(h1));
    *(__half2*)(lo + o + 2) = __floats2half2_rn(v.z - __half2float(h2), v.w - __half2float(h3));
}

__global__ void dinv_kernel(const float* __restrict__ deg, float* __restrict__ dinv) {
    int i = blockIdx.x * 256 + threadIdx.x;
    dinv[i] = 1.0f / sqrtf(deg[i]);
}

// W[f,g] -> WT[g,f] single fp16
__global__ void wtrans_kernel(const float* __restrict__ W, __half* __restrict__ hi) {
    __shared__ float tsm[32][33];
    int g0 = blockIdx.x * 32, f0 = blockIdx.y * 32;
#pragma unroll
    for (int k = 0; k < 4; k++) {
        int f = f0 + threadIdx.y + k * 8;
        tsm[threadIdx.x][threadIdx.y + k * 8] = W[(size_t)f * F_ + g0 + threadIdx.x];
    }
    __syncthreads();
#pragma unroll
    for (int k = 0; k < 4; k++) {
        int gg = g0 + threadIdx.y + k * 8;
        hi[(size_t)gg * F_ + f0 + threadIdx.x] = __float2half_rn(tsm[threadIdx.y + k * 8][threadIdx.x]);
    }
}

// ============================================================================
extern "C" void kernel_launch(void* const* d_in, const int* in_sizes, int n_in,
                              void* d_out, int out_size) {
    const float* x  = (const float*)d_in[0];
    const float* W1 = (const float*)d_in[1];
    const float* b1 = (const float*)d_in[2];
    const float* W2 = (const float*)d_in[3];
    const float* b2 = (const float*)d_in[4];
    float* out = (float*)d_out;

    __half *pA, *pxhi, *pxlo, *pgT, *ph2, *pWT1, *pWT2;
    float *pinvn, *pdeg, *pdinv;
    cudaGetSymbolAddress((void**)&pA,    g_A);
    cudaGetSymbolAddress((void**)&pinvn, g_invn);
    cudaGetSymbolAddress((void**)&pdeg,  g_deg);
    cudaGetSymbolAddress((void**)&pdinv, g_dinv);
    cudaGetSymbolAddress((void**)&pxhi,  g_xhi);
    cudaGetSymbolAddress((void**)&pxlo,  g_xlo);
    cudaGetSymbolAddress((void**)&pgT,   g_gT);
    cudaGetSymbolAddress((void**)&ph2,   g_h2);
    cudaGetSymbolAddress((void**)&pWT1,  g_WT1);
    cudaGetSymbolAddress((void**)&pWT2,  g_WT2);

    const int smem0 = 4 * 3 * (128 * 32 * 2);   // 98304 B (GRAM: 4 ops, KC32)
    const int smem1 = 2 * 3 * (128 * 64 * 2);   // 98304 B (HWT/AH: 2 ops, KC64)
    cudaFuncSetAttribute(mma_gemm<0>, cudaFuncAttributeMaxDynamicSharedMemorySize, smem0);
    cudaFuncSetAttribute(mma_gemm<1>, cudaFuncAttributeMaxDynamicSharedMemorySize, smem1);
    cudaFuncSetAttribute(mma_gemm<2>, cudaFuncAttributeMaxDynamicSharedMemorySize, smem1);
    cudaFuncSetAttribute(mma_gemm<3>, cudaFuncAttributeMaxDynamicSharedMemorySize, smem1);

    const int NBLK = C_ / 128;                       // 16
    const int NTRI = NBLK * (NBLK + 1) / 2;          // 136

    // ---- input-only preprocessing (no cross dependencies) ----
    wtrans_kernel<<<dim3(F_ / 32, F_ / 32), dim3(32, 8)>>>(W1, pWT1);
    wtrans_kernel<<<dim3(F_ / 32, F_ / 32), dim3(32, 8)>>>(W2, pWT2);
    norm_split<<<B_ * C_, 128>>>(x, pinvn, pxhi, pxlo, pdeg);

    // ---- Laplacian ----
    mma_gemm<0><<<dim3(NTRI, 1, B_), 256, smem0>>>(
        pxhi, pxlo, pxhi, pxlo, F_, F_, F_,
        (size_t)C_ * F_, (size_t)C_ * F_, pinvn, C_, nullptr,
        pA, C_, (size_t)C_ * C_, pdeg);
    dinv_kernel<<<(B_ * C_) / 256, 256>>>(pdeg, pdinv);

    // ---- layer 1: relu(L @ (x @ W1) + b1) ----
    mma_gemm<2><<<dim3(F_ / 128, (B_ * C_) / 128, 1), 256, smem1>>>(
        pxhi, nullptr, pWT1, nullptr, F_, F_, F_,
        0, 0, pdinv, 0, nullptr,
        pgT, C_, 0, nullptr);
    mma_gemm<1><<<dim3(F_ / 128, C_ / 128, B_), 256, smem1>>>(
        pA, nullptr, pgT, nullptr, C_, C_, C_,
        (size_t)C_ * C_, (size_t)F_ * C_, pdinv, C_, b1,
        ph2, F_, (size_t)C_ * F_, nullptr);

    // ---- layer 2: relu(L @ (h2 @ W2) + b2) ----
    mma_gemm<2><<<dim3(F_ / 128, (B_ * C_) / 128, 1), 256, smem1>>>(
        ph2, nullptr, pWT2, nullptr, F_, F_, F_,
        0, 0, pdinv, 0, nullptr,
        pgT, C_, 0, nullptr);
    mma_gemm<3><<<dim3(F_ / 128, C_ / 128, B_), 256, smem1>>>(
        pA, nullptr, pgT, nullptr, C_, C_, C_,
        (size_t)C_ * C_, (size_t)F_ * C_, pdinv, C_, b2,
        out, F_, (size_t)C_ * F_, nullptr);
}